// round 17
// baseline (speedup 1.0000x reference)
#include <cuda_runtime.h>
#include <math.h>

typedef unsigned long long ull;

#define B      8
#define DIM    1024
#define HID    512
#define NB     16
#define SEQ    2048
#define TLEN   4096
#define NSTEPS (TLEN - SEQ)
#define NBLK   128
#define NTHR   512
#define NGRP   16
#define GPAD   32
#define NREP   8

// barrier ids
#define BA1 0
#define BA2 1
#define BB1 2
#define BB2 3

// smem offsets (floats)
#define OFF_D1    0        // 16384: D1own [8jl][2048] (init only)
#define OFF_G     16384    // 16384: Gt/Gb own [8jl][2048]
#define OFF_W2    32768    // 8192 : W1own temp -> D2own [8il][1024]
#define OFF_E     40960    // 4096 : E=D2@W1 own [4ml][1024]
#define OFF_RED   45056    // 3584 : per chain 1792: E 256 | Gt 512 | Gb 512 | D2 512
#define OFF_C     48640    // 256  : s_c[chain][parity][64]
#define OFF_BAS   48896    // 128
#define OFF_BD1T  49024    // 128
#define OFF_BD1B  49152    // 128
#define OFF_BASW1 49280    // 64
#define OFF_G8    49344    // 32
#define OFF_WC2   49376    // 64
#define OFF_NOWN  49440    // 64
#define OFF_Z     49504    // 32
#define OFF_WP    49536    // 64
#define OFF_VP    49600    // 64
#define OFF_BB    49664    // 64
#define SMEM_FLOATS 49728  // ~194 KB

__device__ float g_h1[2][B * DIM];
__device__ float g_coefR[2][2][NREP][4 * NB];   // [chain][parity][rep][64]
__device__ unsigned int g_bcnt[4 * NGRP * GPAD];
__device__ unsigned int g_done;

__device__ __forceinline__ void fma2(ull& d, ull a, ull b) {
    asm("fma.rn.f32x2 %0, %1, %2, %0;" : "+l"(d) : "l"(a), "l"(b));
}
__device__ __forceinline__ float f2sum(ull v) {
    float lo, hi;
    asm("mov.b64 {%0,%1}, %2;" : "=f"(lo), "=f"(hi) : "l"(v));
    return lo + hi;
}

__device__ __forceinline__ void bar_arrive(int i) {
    __syncthreads();
    if (threadIdx.x == 0)
        asm volatile("red.release.gpu.global.add.u32 [%0], %1;"
                     :: "l"(&g_bcnt[(i * NGRP + (blockIdx.x & (NGRP - 1))) * GPAD]),
                        "r"(1u) : "memory");
}
__device__ __forceinline__ void bar_wait(int i, unsigned tgt) {
    if (threadIdx.x < NGRP) {
        const unsigned* p = &g_bcnt[(i * NGRP + threadIdx.x) * GPAD];
        unsigned v;
        do {
            asm volatile("ld.acquire.gpu.global.u32 %0, [%1];" : "=r"(v) : "l"(p) : "memory");
        } while (v < tgt);
    }
    __syncthreads();
}

__global__ void copy_kernel(const float4* __restrict__ x4, float4* __restrict__ out4) {
    size_t q = (size_t)blockIdx.x * blockDim.x + threadIdx.x;
    int b = (int)(q >> 19);
    size_t r = q & 524287;
    out4[((size_t)b << 20) + r] = x4[q];
}

// act: 4 packed pairs = 16 k-elems per thread (kg in 0..127, b4 = t&3)
__device__ __forceinline__ void load_act(ull a[4], const float* __restrict__ row, int kg) {
    #pragma unroll
    for (int q = 0; q < 2; ++q) {
        float4 v = __ldg(reinterpret_cast<const float4*>(row + q * 512 + kg * 4));
        asm("mov.b64 %0,{%1,%2};" : "=l"(a[2 * q])     : "f"(v.x), "f"(v.y));
        asm("mov.b64 %0,{%1,%2};" : "=l"(a[2 * q + 1]) : "f"(v.z), "f"(v.w));
    }
}
template <int N>
__device__ __forceinline__ void accN(ull* acc, const ull a[4],
                                     const float* s_w, int ws, int wo, int kg) {
    #pragma unroll
    for (int q = 0; q < 2; ++q) {
        const int k = q * 512 + kg * 4;
        #pragma unroll
        for (int o = 0; o < N; ++o) {
            ulonglong2 w = *reinterpret_cast<const ulonglong2*>(s_w + o * ws + wo + k);
            fma2(acc[o], w.x, a[2 * q]);
            fma2(acc[o], w.y, a[2 * q + 1]);
        }
    }
}
template <int N>
__device__ __forceinline__ void reduceN(float* red, ull* acc, int t) {
    const int b4 = t & 3;
    #pragma unroll
    for (int o = 0; o < N; ++o) {
        float r = f2sum(acc[o]);
        r += __shfl_xor_sync(0xffffffffu, r, 4);
        r += __shfl_xor_sync(0xffffffffu, r, 8);
        r += __shfl_xor_sync(0xffffffffu, r, 16);
        if ((t & 31) < 4) red[((t >> 5) * 4 + b4) * N + o] = r;
    }
}
__device__ __forceinline__ float dot1024(const float* __restrict__ gsrc, const float* scol) {
    const float4* g4 = reinterpret_cast<const float4*>(gsrc);
    float a0 = 0.f, a1 = 0.f, a2 = 0.f, a3 = 0.f;
    for (int k4 = 0; k4 < 256; ++k4) {
        float4 v = __ldg(g4 + k4);
        const float* w = scol + k4 * 4;
        a0 += v.x * w[0]; a1 += v.y * w[1]; a2 += v.z * w[2]; a3 += v.w * w[3];
    }
    return (a0 + a1) + (a2 + a3);
}

// segA: E matvec -> z/gelu -> coef partial atomics (per chain)
__device__ __forceinline__ void phaseA(float* sm, const ull act[4], int chain, int p,
                                       int bid, int t, int kg) {
    const int co = chain * 4;
    float* red = sm + OFF_RED + chain * 1792;
    const float* cm1 = sm + OFF_C + chain * 128 + (1 - p) * 64;
    {
        ull a4[4] = {0ull, 0ull, 0ull, 0ull};
        accN<4>(a4, act, sm + OFF_E, 1024, 0, kg);
        reduceN<4>(red, a4, t);
    }
    __syncthreads();
    if (t < 16) {
        int bb4 = t >> 2, ml = t & 3;
        float sum = 0.f;
        #pragma unroll
        for (int w = 0; w < 16; ++w) sum += red[(w * 4 + bb4) * 4 + ml];
        float zc = 0.f;
        #pragma unroll
        for (int c = 0; c < NB; ++c)
            zc += cm1[bb4 * NB + c] * sm[OFF_BASW1 + c * 4 + ml];
        int zi = (co + bb4) * 4 + ml;
        float z = sm[OFF_Z + zi] + sum + 0.1f * zc + sm[OFF_BB + 36 + ml];
        sm[OFF_Z + zi] = z;
        sm[OFF_G8 + zi] = 0.5f * z * (1.0f + erff(z * 0.70710678118654752f));
    }
    __syncthreads();
    if (t < 64) {
        int bb4 = t >> 4, cc = t & 15;
        float a = 0.f;
        #pragma unroll
        for (int ml = 0; ml < 4; ++ml)
            a += sm[OFF_G8 + (co + bb4) * 4 + ml] * sm[OFF_WC2 + ml * NB + cc];
        atomicAdd(&g_coefR[chain][p][bid & (NREP - 1)][t], a);
    }
}

// segB: Gt / Gb / D2own matvecs from act registers (per chain)
__device__ __forceinline__ void phaseB(float* sm, const ull act[4], int chain, int t, int kg) {
    float* red = sm + OFF_RED + chain * 1792;
    {
        ull a8[8] = {0ull,0ull,0ull,0ull,0ull,0ull,0ull,0ull};
        accN<8>(a8, act, sm + OFF_G, 2048, 0, kg);
        reduceN<8>(red + 256, a8, t);
    }
    {
        ull a8[8] = {0ull,0ull,0ull,0ull,0ull,0ull,0ull,0ull};
        accN<8>(a8, act, sm + OFF_G, 2048, 1024, kg);
        reduceN<8>(red + 768, a8, t);
    }
    {
        ull a8[8] = {0ull,0ull,0ull,0ull,0ull,0ull,0ull,0ull};
        accN<8>(a8, act, sm + OFF_W2, 1024, 0, kg);
        reduceN<8>(red + 1280, a8, t);
    }
}

// post-waitX2: gather coef -> tails -> publish h1_{s+1} (per chain)
__device__ __forceinline__ void phaseC(float* sm, int chain, int p, int bid, int t,
                                       float* __restrict__ h1next) {
    const int co = chain * 4;
    float* red = sm + OFF_RED + chain * 1792;
    float* scc = sm + OFF_C + chain * 128;
    if (t < 64) {
        float crep = 0.f;
        #pragma unroll
        for (int r = 0; r < NREP; ++r) crep += g_coefR[chain][p][r][t];
        scc[p * 64 + t] = crep + sm[OFF_BB + 20 + (t & 15)];
    }
    __syncthreads();
    if (t < 32) {
        const int bb4 = t >> 3, jl = t & 7;
        const int si = co * 8 + t;
        float gt = 0.f, gb = 0.f, d2 = 0.f;
        #pragma unroll
        for (int w = 0; w < 16; ++w) {
            gt += red[256  + (w * 4 + bb4) * 8 + jl];
            gb += red[768  + (w * 4 + bb4) * 8 + jl];
            d2 += red[1280 + (w * 4 + bb4) * 8 + jl];
        }
        const float* cm1 = scc + (1 - p) * 64;
        const float* cs  = scc + p * 64;
        float cdT = 0.f, cdB = 0.f, cbas = 0.f, csT = 0.f;
        #pragma unroll
        for (int c = 0; c < NB; ++c) {
            float c1 = cm1[bb4 * NB + c];
            cdT  += c1 * sm[OFF_BD1T + c * 8 + jl];
            cdB  += c1 * sm[OFF_BD1B + c * 8 + jl];
            cbas += c1 * sm[OFF_BAS  + c * 8 + jl];
            csT  += cs[bb4 * NB + c] * sm[OFF_BD1T + c * 8 + jl];
        }
        float wp_new = sm[OFF_WP + si] + gt + sm[OFF_BB + 40 + jl] + 0.1f * cdT;
        float vp_old = sm[OFF_VP + si];
        h1next[(co + bb4) * DIM + bid * 8 + jl] =
            tanhf(wp_new + vp_old + sm[OFF_BB + jl] + 0.1f * (csT + cdB));
        sm[OFF_WP + si]   = wp_new;
        sm[OFF_VP + si]   = vp_old + gb + sm[OFF_BB + 48 + jl] + 0.1f * cdB;
        sm[OFF_NOWN + si] += d2 + sm[OFF_BB + 8 + jl] + 0.1f * cbas;
    }
}

__global__ void __launch_bounds__(NTHR, 1)
extrap_kernel(const float* __restrict__ x, const float* __restrict__ basis,
              const float* __restrict__ W1, const float* __restrict__ b1,
              const float* __restrict__ W2, const float* __restrict__ b2,
              const float* __restrict__ D1, const float* __restrict__ bD1,
              const float* __restrict__ D2, const float* __restrict__ bD2,
              float* __restrict__ out)
{
    extern __shared__ float sm[];
    float* s_D1 = sm + OFF_D1;
    float* s_G  = sm + OFF_G;
    float* s_w2 = sm + OFF_W2;
    float* s_E  = sm + OFF_E;

    const int bid = blockIdx.x;
    const int t   = threadIdx.x;
    const int b4  = t & 3;
    const int kg  = t >> 2;                 // 0..127

    // ===== init 1: loads =====
    for (int idx = t; idx < 8 * 2048; idx += NTHR) {
        int jl = idx & 7, kk = idx >> 3;
        s_D1[jl * 2048 + kk] = __ldg(D1 + (size_t)kk * DIM + bid * 8 + jl);
    }
    for (int idx = t; idx < 4 * 1024; idx += NTHR) {
        int ml = idx & 3, kk = idx >> 2;
        s_w2[ml * 1024 + kk] = __ldg(W1 + (size_t)kk * HID + bid * 4 + ml);
    }
    if (t < 128) sm[OFF_BAS + t] = __ldg(basis + (size_t)(t >> 3) * DIM + bid * 8 + (t & 7));
    else if (t < 192) {
        int tt = t - 128;
        sm[OFF_NOWN + tt] = __ldg(x + ((size_t)(tt >> 3) * SEQ + SEQ - 1) * DIM + bid * 8 + (tt & 7));
    } else if (t < 256) {
        int tt = t - 192;
        sm[OFF_WC2 + tt] = __ldg(W2 + (size_t)(bid * 4 + (tt >> 4)) * NB + (tt & 15));
    } else if (t < 264)  sm[OFF_BB + t - 256]      = __ldg(bD1 + bid * 8 + (t - 256));
    else if (t < 272)    sm[OFF_BB + t - 264 + 8]  = __ldg(bD2 + bid * 8 + (t - 264));
    else if (t < 288)    sm[OFF_BB + 20 + t - 272] = __ldg(b2 + (t - 272));
    for (int idx = t; idx < 256; idx += NTHR) sm[OFF_C + idx] = 0.f;
    if (bid < NREP)
        for (int idx = t; idx < 256; idx += NTHR)
            g_coefR[idx >> 7][(idx >> 6) & 1][bid][idx & 63] = 0.f;
    __syncthreads();

    // ===== init 2a: big dots =====
    if (t < 256) {
        int half = t >> 7, c = (t >> 3) & 15, jl = t & 7;
        float v = dot1024(basis + (size_t)c * DIM, s_D1 + jl * 2048 + half * 1024);
        sm[(half ? OFF_BD1B : OFF_BD1T) + c * 8 + jl] = v;
    } else if (t < 320) {
        int tt = t - 256;
        sm[OFF_BASW1 + tt] = dot1024(basis + (size_t)(tt >> 2) * DIM, s_w2 + (tt & 3) * 1024);
    } else if (t < 384) {
        int tt = t - 320;
        sm[OFF_WP + tt] = dot1024(x + ((size_t)(tt >> 3) * SEQ + SEQ - 1) * DIM,
                                  s_D1 + (tt & 7) * 2048);
    } else if (t < 448) {
        int tt = t - 384;
        sm[OFF_VP + tt] = dot1024(x + ((size_t)(tt >> 3) * SEQ + SEQ - 1) * DIM,
                                  s_D1 + (tt & 7) * 2048 + 1024);
    } else {
        int tt = t - 448;
        sm[OFF_RED + tt] = dot1024(x + ((size_t)(tt >> 3) * SEQ + SEQ - 2) * DIM,
                                   s_D1 + (tt & 7) * 2048 + 1024);
    }
    __syncthreads();

    // ===== init 2b: tiny dots + h1_0 =====
    if (t < 32) {
        float v = dot1024(x + ((size_t)(t >> 2) * SEQ + SEQ - 1) * DIM, s_w2 + (t & 3) * 1024);
        sm[OFF_Z + t] = v + __ldg(b1 + bid * 4 + (t & 3));
    } else if (t < 36) {
        sm[OFF_BB + 36 + (t - 32)] = dot1024(bD2, s_w2 + (t - 32) * 1024);
    } else if (t < 44) {
        sm[OFF_BB + 40 + (t - 36)] = dot1024(bD2, s_D1 + (t - 36) * 2048);
    } else if (t < 52) {
        sm[OFF_BB + 48 + (t - 44)] = dot1024(bD2, s_D1 + (t - 44) * 2048 + 1024);
    } else if (t >= 64 && t < 128) {
        int tt = t - 64;
        g_h1[0][(tt >> 3) * DIM + bid * 8 + (tt & 7)] =
            tanhf(sm[OFF_WP + tt] + sm[OFF_RED + tt] + sm[OFF_BB + (tt & 7)]);
    }
    __syncthreads();

    // ===== init 3: Gt/Gb/E = D2 @ [D1t|D1b|W1] own cols =====
    {
        const int wrp = t >> 5, lane = t & 31;
        for (int g = 0; g < 16; ++g) {
            const int k0 = (wrp * 16 + g) * 4;
            #pragma unroll
            for (int os = 0; os < 4; ++os) {
                float acc[20];
                #pragma unroll
                for (int q = 0; q < 20; ++q) acc[q] = 0.f;
                for (int c8 = 0; c8 < 8; ++c8) {
                    const int i4 = c8 * 32 + lane;
                    float4 wv[5];
                    #pragma unroll
                    for (int c = 0; c < 5; ++c) {
                        const int o = os * 5 + c;
                        const float* wptr = (o < 8)
                            ? (s_D1 + o * 2048 + i4 * 4)
                            : (o < 16 ? (s_D1 + (o - 8) * 2048 + 1024 + i4 * 4)
                                      : (s_w2 + (o - 16) * 1024 + i4 * 4));
                        wv[c] = *reinterpret_cast<const float4*>(wptr);
                    }
                    #pragma unroll
                    for (int r = 0; r < 4; ++r) {
                        float4 d = __ldg(reinterpret_cast<const float4*>(
                                             D2 + (size_t)(k0 + r) * DIM) + i4);
                        #pragma unroll
                        for (int c = 0; c < 5; ++c)
                            acc[r * 5 + c] += d.x * wv[c].x + d.y * wv[c].y
                                            + d.z * wv[c].z + d.w * wv[c].w;
                    }
                }
                #pragma unroll
                for (int rc = 0; rc < 20; ++rc) {
                    float v = acc[rc];
                    #pragma unroll
                    for (int off = 16; off; off >>= 1)
                        v += __shfl_xor_sync(0xffffffffu, v, off);
                    if (lane == 0) {
                        const int r = rc / 5, c = rc % 5;
                        const int o = os * 5 + c, k = k0 + r;
                        if (o < 8)       s_G[o * 2048 + k] = v;
                        else if (o < 16) s_G[(o - 8) * 2048 + 1024 + k] = v;
                        else             s_E[(o - 16) * 1024 + k] = v;
                    }
                }
            }
        }
    }
    __syncthreads();

    // ===== init 4: D2own -> s_w2; arrive both chains =====
    for (int idx = t; idx < 8 * 1024; idx += NTHR) {
        int il = idx & 7, kk = idx >> 3;
        s_w2[il * 1024 + kk] = __ldg(D2 + (size_t)kk * DIM + bid * 8 + il);
    }
    bar_arrive(BA1);
    bar_arrive(BB1);

    // ================= interleaved step loop =================
    for (int s = 0; s < NSTEPS; ++s) {
        const int p = s & 1;
        const unsigned tgt = (unsigned)(s + 1) * (NBLK / NGRP);

        // ---- chain A front ----
        bar_wait(BA1, tgt);
        if (bid < NREP && t >= 448) g_coefR[0][1 - p][bid][t - 448] = 0.f;
        ull actA[4];
        load_act(actA, g_h1[p] + b4 * DIM, kg);
        phaseA(sm, actA, 0, p, bid, t, kg);
        bar_arrive(BA2);
        phaseB(sm, actA, 0, t, kg);

        // ---- chain B front ----
        bar_wait(BB1, tgt);
        if (bid < NREP && t >= 448) g_coefR[1][1 - p][bid][t - 448] = 0.f;
        ull actB[4];
        load_act(actB, g_h1[p] + (4 + b4) * DIM, kg);
        phaseA(sm, actB, 1, p, bid, t, kg);
        bar_arrive(BB2);
        phaseB(sm, actB, 1, t, kg);

        // ---- chain A tail ----
        bar_wait(BA2, tgt);
        phaseC(sm, 0, p, bid, t, g_h1[1 - p]);
        bar_arrive(BA1);
        if (t >= 32 && t < 40) {       // output rows, chain A (after arrive's sync)
            int tt = t - 32, bb4 = tt >> 1, hf = tt & 1;
            int c0 = bid * 8 + hf * 4;
            const float* cs = sm + OFF_C + p * 64;
            float o[4];
            #pragma unroll
            for (int xi = 0; xi < 4; ++xi) {
                float corr = 0.f;
                #pragma unroll
                for (int c = 0; c < NB; ++c)
                    corr += cs[bb4 * NB + c] * sm[OFF_BAS + c * 8 + hf * 4 + xi];
                o[xi] = sm[OFF_NOWN + bb4 * 8 + hf * 4 + xi] + 0.1f * corr;
            }
            *reinterpret_cast<float4*>(out + ((size_t)bb4 * TLEN + SEQ + s) * DIM + c0) =
                make_float4(o[0], o[1], o[2], o[3]);
        }

        // ---- chain B tail ----
        bar_wait(BB2, tgt);
        phaseC(sm, 1, p, bid, t, g_h1[1 - p]);
        bar_arrive(BB1);
        if (t >= 32 && t < 40) {       // output rows, chain B
            int tt = t - 32, bb4 = tt >> 1, hf = tt & 1;
            int bb = 4 + bb4;
            int c0 = bid * 8 + hf * 4;
            const float* cs = sm + OFF_C + 128 + p * 64;
            float o[4];
            #pragma unroll
            for (int xi = 0; xi < 4; ++xi) {
                float corr = 0.f;
                #pragma unroll
                for (int c = 0; c < NB; ++c)
                    corr += cs[bb4 * NB + c] * sm[OFF_BAS + c * 8 + hf * 4 + xi];
                o[xi] = sm[OFF_NOWN + bb * 8 + hf * 4 + xi] + 0.1f * corr;
            }
            *reinterpret_cast<float4*>(out + ((size_t)bb * TLEN + SEQ + s) * DIM + c0) =
                make_float4(o[0], o[1], o[2], o[3]);
        }
    }

    // ================= done barrier + counter reset =================
    __syncthreads();
    if (t == 0) {
        asm volatile("red.release.gpu.global.add.u32 [%0], %1;"
                     :: "l"(&g_done), "r"(1u) : "memory");
        if (bid == 0) {
            unsigned v;
            do {
                asm volatile("ld.acquire.gpu.global.u32 %0, [%1];"
                             : "=r"(v) : "l"(&g_done) : "memory");
            } while (v < (unsigned)NBLK);
            for (int i = 0; i < 4 * NGRP; ++i) g_bcnt[i * GPAD] = 0;
            g_done = 0;
        }
    }
}

extern "C" void kernel_launch(void* const* d_in, const int* in_sizes, int n_in,
                              void* d_out, int out_size) {
    const float* x     = (const float*)d_in[0];
    const float* basis = (const float*)d_in[1];
    const float* W1    = (const float*)d_in[2];
    const float* b1    = (const float*)d_in[3];
    const float* W2    = (const float*)d_in[4];
    const float* b2v   = (const float*)d_in[5];
    const float* D1    = (const float*)d_in[6];
    const float* bD1   = (const float*)d_in[7];
    const float* D2    = (const float*)d_in[8];
    const float* bD2   = (const float*)d_in[9];
    float* out = (float*)d_out;

    copy_kernel<<<4096, 1024>>>((const float4*)x, (float4*)out);

    size_t smem_bytes = (size_t)SMEM_FLOATS * sizeof(float);   // ~194 KB
    cudaFuncSetAttribute(extrap_kernel, cudaFuncAttributeMaxDynamicSharedMemorySize,
                         (int)smem_bytes);
    extrap_kernel<<<NBLK, NTHR, smem_bytes>>>(x, basis, W1, b1, W2, b2v,
                                              D1, bD1, D2, bD2, out);
}